// round 1
// baseline (speedup 1.0000x reference)
#include <cuda_runtime.h>
#include <math.h>
#include <stdint.h>

// Problem dims
#define BB 512
#define II 1024
#define HH_ 1024     // main hidden H
#define HHH 256      // meta hidden HH
#define EE 64
#define XHK 2048     // I + H
#define G4H 4096     // 4*H
#define G4HH 1024    // 4*HH

// Output layout: main_h_new, main_c_new, meta_h_new, meta_c_new
#define OFF_MAINH 0
#define OFF_MAINC (BB*HH_)
#define OFF_METAH (2*BB*HH_)
#define OFF_METAC (2*BB*HH_ + BB*HHH)

// Scratch (device globals; no dynamic allocation allowed)
__device__ float g_xh[BB * XHK];          // [512,2048]
__device__ float g_metapre[BB * G4HH];    // [512,1024]
__device__ float g_z[BB * 192];           // [512,192] = zi|zH|zb
__device__ float g_M1[BB * G4H];          // input @ W_iH^T
__device__ float g_M2[BB * G4H];          // main_h @ W_HH^T
__device__ float g_Z1[BB * G4H];          // zi @ W_dziH^T
__device__ float g_Z2[BB * G4H];          // zH @ W_dzHH^T
__device__ float g_Z3[BB * G4H];          // zb @ W_bzH^T + bias

__device__ __forceinline__ float sigm(float x) { return 1.0f / (1.0f + expf(-x)); }

// ---------------------------------------------------------------------------
// concat [input | main_h] -> g_xh
// ---------------------------------------------------------------------------
__global__ void concat_k(const float* __restrict__ in, const float* __restrict__ mh) {
    int idx = blockIdx.x * 256 + threadIdx.x;       // 512*2048 total
    int b = idx >> 11, c = idx & 2047;
    g_xh[idx] = (c < II) ? in[b * II + c] : mh[b * HH_ + (c - II)];
}

// ---------------------------------------------------------------------------
// Generic SGEMM: C[M,N] (+= / =) A[M,K](lda) @ W[N,K]^T  (+bias[n])
// BM=BN=64, BK=16, 256 threads, 4x4 per-thread microtile. All dims divide.
// ---------------------------------------------------------------------------
#define BM 64
#define BN 64
#define BK 16

__global__ __launch_bounds__(256) void sgemm_nt(
    const float* __restrict__ A, int lda,
    const float* __restrict__ W,
    const int* __restrict__ task, size_t task_stride,
    float* __restrict__ C,
    const float* __restrict__ bias,
    int M, int N, int K, int accumulate)
{
    if (task) W += (size_t)(*task) * task_stride;

    __shared__ float As[BK][BM];
    __shared__ float Ws[BK][BN];

    const int bm = blockIdx.y * BM;
    const int bn = blockIdx.x * BN;
    const int tid = threadIdx.x;
    const int tx = tid & 15;   // n-dir, 16
    const int ty = tid >> 4;   // m-dir, 16

    float acc[4][4];
#pragma unroll
    for (int i = 0; i < 4; i++)
#pragma unroll
        for (int j = 0; j < 4; j++) acc[i][j] = 0.0f;

    const int lr = tid >> 2;       // 0..63 tile row for loads
    const int lv = tid & 3;        // 0..3 float4 within 16-col slab

    for (int k0 = 0; k0 < K; k0 += BK) {
        float4 a = *reinterpret_cast<const float4*>(&A[(size_t)(bm + lr) * lda + k0 + lv * 4]);
        float4 w = *reinterpret_cast<const float4*>(&W[(size_t)(bn + lr) * K + k0 + lv * 4]);
        As[lv * 4 + 0][lr] = a.x; As[lv * 4 + 1][lr] = a.y;
        As[lv * 4 + 2][lr] = a.z; As[lv * 4 + 3][lr] = a.w;
        Ws[lv * 4 + 0][lr] = w.x; Ws[lv * 4 + 1][lr] = w.y;
        Ws[lv * 4 + 2][lr] = w.z; Ws[lv * 4 + 3][lr] = w.w;
        __syncthreads();

#pragma unroll
        for (int kk = 0; kk < BK; kk++) {
            float4 av = *reinterpret_cast<const float4*>(&As[kk][ty * 4]);
            float4 wv = *reinterpret_cast<const float4*>(&Ws[kk][tx * 4]);
            float ar[4] = {av.x, av.y, av.z, av.w};
            float wr[4] = {wv.x, wv.y, wv.z, wv.w};
#pragma unroll
            for (int i = 0; i < 4; i++)
#pragma unroll
                for (int j = 0; j < 4; j++)
                    acc[i][j] += ar[i] * wr[j];
        }
        __syncthreads();
    }

#pragma unroll
    for (int i = 0; i < 4; i++) {
        int m = bm + ty * 4 + i;
#pragma unroll
        for (int j = 0; j < 4; j++) {
            int n = bn + tx * 4 + j;
            float v = acc[i][j];
            if (bias) v += bias[n];
            size_t off = (size_t)m * N + n;
            if (accumulate) v += C[off];
            C[off] = v;
        }
    }
}

// ---------------------------------------------------------------------------
// meta LSTM gates: metapre [512,1024] + meta_c -> meta_h_new, meta_c_new
// ---------------------------------------------------------------------------
__global__ void meta_gates_k(const float* __restrict__ meta_c, float* __restrict__ out) {
    int idx = blockIdx.x * 256 + threadIdx.x;      // 512*256
    int b = idx >> 8, j = idx & 255;
    const float* row = g_metapre + (size_t)b * G4HH;
    float mi = row[j], mf = row[j + 256], mg = row[j + 512], mo = row[j + 768];
    float c = sigm(mf) * meta_c[idx] + sigm(mi) * tanhf(mg);
    float h = sigm(mo) * tanhf(c);
    out[OFF_METAH + idx] = h;
    out[OFF_METAC + idx] = c;
}

// ---------------------------------------------------------------------------
// z = meta_h_new @ [W_hzi;W_hzH;W_hzb]^T (+bias_i,+bias_H,+0) -> g_z [512,192]
// one block per batch row, 192 threads
// ---------------------------------------------------------------------------
__global__ void z_k(const float* __restrict__ out /*reads meta_h_new*/,
                    const float* __restrict__ w_hzi, const float* __restrict__ w_hzH,
                    const float* __restrict__ w_hzb,
                    const float* __restrict__ bias_i, const float* __restrict__ bias_H)
{
    __shared__ float mh[HHH];
    int b = blockIdx.x;
    int t = threadIdx.x;
    for (int k = t; k < HHH; k += 192) mh[k] = out[OFF_METAH + (size_t)b * HHH + k];
    __syncthreads();

    const float* wrow;
    float bv;
    if (t < 64)      { wrow = w_hzi + (size_t)t * HHH;        bv = bias_i[t]; }
    else if (t < 128){ wrow = w_hzH + (size_t)(t - 64) * HHH; bv = bias_H[t - 64]; }
    else             { wrow = w_hzb + (size_t)(t - 128) * HHH; bv = 0.0f; }

    float s = bv;
#pragma unroll 8
    for (int k = 0; k < HHH; k++) s += mh[k] * wrow[k];
    g_z[(size_t)b * 192 + t] = s;
}

// ---------------------------------------------------------------------------
// combine: pre = Z1*M1 + Z2*M2 + Z3 ; main gates -> main_h_new, main_c_new
// ---------------------------------------------------------------------------
__global__ void combine_k(const float* __restrict__ main_c, float* __restrict__ out) {
    int idx = blockIdx.x * 256 + threadIdx.x;      // 512*1024
    int b = idx >> 10, n = idx & 1023;
    size_t base = (size_t)b * G4H + n;
    float pre[4];
#pragma unroll
    for (int g = 0; g < 4; g++) {
        size_t o = base + (size_t)g * HH_;
        pre[g] = g_Z1[o] * g_M1[o] + g_Z2[o] * g_M2[o] + g_Z3[o];
    }
    float c = sigm(pre[1]) * main_c[idx] + sigm(pre[0]) * tanhf(pre[2]);
    float h = sigm(pre[3]) * tanhf(c);
    out[OFF_MAINH + idx] = h;
    out[OFF_MAINC + idx] = c;
}

// ---------------------------------------------------------------------------
// launch
// ---------------------------------------------------------------------------
extern "C" void kernel_launch(void* const* d_in, const int* in_sizes, int n_in,
                              void* d_out, int out_size)
{
    const float* input      = (const float*)d_in[0];
    const float* main_h     = (const float*)d_in[1];
    const float* main_c     = (const float*)d_in[2];
    const float* meta_h     = (const float*)d_in[3];
    const float* meta_c     = (const float*)d_in[4];
    const int*   task       = (const int*)d_in[5];
    const float* w_iH       = (const float*)d_in[6];   // [4,4096,1024]
    const float* w_HH       = (const float*)d_in[7];   // [4,4096,1024]
    const float* w_ih       = (const float*)d_in[8];   // [1024,2048]
    const float* w_hh       = (const float*)d_in[9];   // [1024,256]
    const float* w_hzi      = (const float*)d_in[10];  // [64,256]
    const float* w_hzH      = (const float*)d_in[11];
    const float* w_hzb      = (const float*)d_in[12];
    const float* w_dziH     = (const float*)d_in[13];  // [4096,64]
    const float* w_dzHH     = (const float*)d_in[14];
    const float* w_bzH      = (const float*)d_in[15];
    const float* bias_i     = (const float*)d_in[16];  // [64]
    const float* bias_H     = (const float*)d_in[17];  // [64]
    const float* bias       = (const float*)d_in[18];  // [4096]
    const float* bias_hyper = (const float*)d_in[19];  // [1024]
    float* out = (float*)d_out;

    // scratch symbol addresses (query API; no allocation, capture-safe)
    float *p_xh, *p_metapre, *p_z, *p_M1, *p_M2, *p_Z1, *p_Z2, *p_Z3;
    cudaGetSymbolAddress((void**)&p_xh,      g_xh);
    cudaGetSymbolAddress((void**)&p_metapre, g_metapre);
    cudaGetSymbolAddress((void**)&p_z,       g_z);
    cudaGetSymbolAddress((void**)&p_M1,      g_M1);
    cudaGetSymbolAddress((void**)&p_M2,      g_M2);
    cudaGetSymbolAddress((void**)&p_Z1,      g_Z1);
    cudaGetSymbolAddress((void**)&p_Z2,      g_Z2);
    cudaGetSymbolAddress((void**)&p_Z3,      g_Z3);

    const size_t taskStride = (size_t)G4H * II; // 4096*1024

    // 1) concat
    concat_k<<<(BB * XHK) / 256, 256>>>(input, main_h);

    // 2) metapre = xh @ w_ih^T + bias_hyper
    sgemm_nt<<<dim3(G4HH / BN, BB / BM), 256>>>(p_xh, XHK, w_ih, nullptr, 0,
                                                p_metapre, bias_hyper,
                                                BB, G4HH, XHK, 0);
    // 3) metapre += meta_h @ w_hh^T
    sgemm_nt<<<dim3(G4HH / BN, BB / BM), 256>>>(meta_h, HHH, w_hh, nullptr, 0,
                                                p_metapre, nullptr,
                                                BB, G4HH, HHH, 1);
    // 4) meta gates
    meta_gates_k<<<(BB * HHH) / 256, 256>>>(meta_c, out);

    // 5) z
    z_k<<<BB, 192>>>(out, w_hzi, w_hzH, w_hzb, bias_i, bias_H);

    // 6) M1 = input @ W_iH[task]^T
    sgemm_nt<<<dim3(G4H / BN, BB / BM), 256>>>(input, II, w_iH, task, taskStride,
                                               p_M1, nullptr,
                                               BB, G4H, II, 0);
    // 7) M2 = main_h @ W_HH[task]^T
    sgemm_nt<<<dim3(G4H / BN, BB / BM), 256>>>(main_h, HH_, w_HH, task, taskStride,
                                               p_M2, nullptr,
                                               BB, G4H, HH_, 0);
    // 8) Z1 = zi @ w_dziH^T
    sgemm_nt<<<dim3(G4H / BN, BB / BM), 256>>>(p_z, 192, w_dziH, nullptr, 0,
                                               p_Z1, nullptr,
                                               BB, G4H, EE, 0);
    // 9) Z2 = zH @ w_dzHH^T
    sgemm_nt<<<dim3(G4H / BN, BB / BM), 256>>>(p_z + 64, 192, w_dzHH, nullptr, 0,
                                               p_Z2, nullptr,
                                               BB, G4H, EE, 0);
    // 10) Z3 = zb @ w_bzH^T + bias
    sgemm_nt<<<dim3(G4H / BN, BB / BM), 256>>>(p_z + 128, 192, w_bzH, nullptr, 0,
                                               p_Z3, bias,
                                               BB, G4H, EE, 0);
    // 11) combine + main gates
    combine_k<<<(BB * HH_) / 256, 256>>>(main_c, out);
}

// round 4
// speedup vs baseline: 3.1972x; 3.1972x over previous
#include <cuda_runtime.h>
#include <cuda_bf16.h>
#include <math.h>
#include <stdint.h>

// ---------------------------------------------------------------------------
// dims / output layout
// ---------------------------------------------------------------------------
#define OFF_MAINH 0
#define OFF_MAINC (512*1024)
#define OFF_METAH (2*512*1024)
#define OFF_METAC (2*512*1024 + 512*256)

__device__ float g_metapre[512*1024];
__device__ float g_z[512*192];
__device__ float g_M1[512*4096];
__device__ float g_M2[512*4096];
__device__ float g_pre[512*4096];

__device__ __forceinline__ uint32_t smem_u32(const void* p) {
    uint32_t a;
    asm("{ .reg .u64 t; cvta.to.shared.u64 t, %1; cvt.u32.u64 %0, t; }"
        : "=r"(a) : "l"(p));
    return a;
}
__device__ __forceinline__ float sigm(float x) { return 1.0f / (1.0f + __expf(-x)); }

// ldmatrix x4 (portable, sm_75+)
__device__ __forceinline__ void ldm4(uint32_t* q, uint32_t addr) {
    asm volatile("ldmatrix.sync.aligned.m8n8.x4.shared.b16 {%0,%1,%2,%3}, [%4];"
        : "=r"(q[0]), "=r"(q[1]), "=r"(q[2]), "=r"(q[3]) : "r"(addr));
}
// mma m16n8k16 bf16 -> f32 (portable, sm_80+)
__device__ __forceinline__ void mma16816(float* d, const uint32_t* a, uint32_t b0, uint32_t b1) {
    asm volatile("mma.sync.aligned.m16n8k16.row.col.f32.bf16.bf16.f32 "
        "{%0,%1,%2,%3},{%4,%5,%6,%7},{%8,%9},{%0,%1,%2,%3};"
        : "+f"(d[0]), "+f"(d[1]), "+f"(d[2]), "+f"(d[3])
        : "r"(a[0]), "r"(a[1]), "r"(a[2]), "r"(a[3]), "r"(b0), "r"(b1));
}
__device__ __forceinline__ uint32_t pk(__nv_bfloat16 a, __nv_bfloat16 b) {
    __nv_bfloat162 t(a, b);
    return *reinterpret_cast<uint32_t*>(&t);
}
// fp32x4 -> (hi bf16x4, lo bf16x4)
__device__ __forceinline__ void cvt_hilo(float4 v, uint2& h, uint2& l) {
    __nv_bfloat16 hx = __float2bfloat16_rn(v.x);
    __nv_bfloat16 hy = __float2bfloat16_rn(v.y);
    __nv_bfloat16 hz = __float2bfloat16_rn(v.z);
    __nv_bfloat16 hw = __float2bfloat16_rn(v.w);
    __nv_bfloat16 lx = __float2bfloat16_rn(v.x - __bfloat162float(hx));
    __nv_bfloat16 ly = __float2bfloat16_rn(v.y - __bfloat162float(hy));
    __nv_bfloat16 lz = __float2bfloat16_rn(v.z - __bfloat162float(hz));
    __nv_bfloat16 lw = __float2bfloat16_rn(v.w - __bfloat162float(hw));
    h = make_uint2(pk(hx, hy), pk(hz, hw));
    l = make_uint2(pk(lx, ly), pk(lz, lw));
}

// ---------------------------------------------------------------------------
// biggemm: C[M,N] = A[M,K] @ W[N,K]^T (+bias), split-bf16 3-product mma.sync
// block 128x128, BK=32, 256 thr (8 warps, warp tile 32x64)
// ---------------------------------------------------------------------------
struct Seg { const float* p; int lda; int kstart; };
struct Job {
    Seg a[3]; int na;
    Seg w[2]; int nw;
    const float* bias;
    float* C;
    int N; int K;
    const float* wTaskBase;
    long long taskStride;
};
struct Jobs3 { Job j[3]; };

#define SA 80                    // smem row stride bytes (32 bf16 + 8 pad)
#define BG_SMEM (4*128*SA)       // Ah, Al, Wh, Wl = 40960

extern __shared__ char dynsm[];

__global__ __launch_bounds__(256)
void biggemm_k(Jobs3 jobs, const int* __restrict__ taskp) {
    Job jb = jobs.j[blockIdx.z];
    const int bn = blockIdx.x * 128;
    if (bn >= jb.N) return;
    const int bm = blockIdx.y * 128;
    if (jb.wTaskBase)
        jb.w[0].p = jb.wTaskBase + (size_t)(*taskp) * jb.taskStride;

    char* Ah = dynsm;
    char* Al = dynsm + 128 * SA;
    char* Wh = dynsm + 2 * 128 * SA;
    char* Wl = dynsm + 3 * 128 * SA;
    const uint32_t sAh = smem_u32(Ah), sAl = smem_u32(Al);
    const uint32_t sWh = smem_u32(Wh), sWl = smem_u32(Wl);

    const int tid = threadIdx.x;
    const int lane = tid & 31, wid = tid >> 5;
    const int wm = wid & 3, wn = wid >> 2;

    const uint32_t loff = ((lane & 7) + ((lane >> 3) & 1) * 8) * SA + (lane >> 4) * 16;

    float acc[2][8][4];
#pragma unroll
    for (int i = 0; i < 2; i++)
#pragma unroll
        for (int j = 0; j < 8; j++)
#pragma unroll
            for (int k = 0; k < 4; k++) acc[i][j][k] = 0.0f;

    const int nch = jb.K / 32;
    float4 ra[4], rw[4];

    auto loadc = [&](int c) {
        const int k0 = c * 32;
        Seg sa = jb.a[0];
        if (jb.na > 1 && k0 >= jb.a[1].kstart) sa = jb.a[1];
        if (jb.na > 2 && k0 >= jb.a[2].kstart) sa = jb.a[2];
        Seg sw = jb.w[0];
        if (jb.nw > 1 && k0 >= jb.w[1].kstart) sw = jb.w[1];
        const int ka = k0 - sa.kstart, kw = k0 - sw.kstart;
#pragma unroll
        for (int i = 0; i < 4; i++) {
            int idx = tid + i * 256;
            int r = idx >> 3, f = idx & 7;
            ra[i] = *reinterpret_cast<const float4*>(sa.p + (size_t)(bm + r) * sa.lda + ka + f * 4);
            rw[i] = *reinterpret_cast<const float4*>(sw.p + (size_t)(bn + r) * sw.lda + kw + f * 4);
        }
    };
    auto storec = [&]() {
#pragma unroll
        for (int i = 0; i < 4; i++) {
            int idx = tid + i * 256;
            int r = idx >> 3, f = idx & 7;
            uint32_t o = r * SA + f * 8;
            uint2 h, l;
            cvt_hilo(ra[i], h, l);
            *reinterpret_cast<uint2*>(Ah + o) = h;
            *reinterpret_cast<uint2*>(Al + o) = l;
            cvt_hilo(rw[i], h, l);
            *reinterpret_cast<uint2*>(Wh + o) = h;
            *reinterpret_cast<uint2*>(Wl + o) = l;
        }
    };

    loadc(0); storec(); __syncthreads();

    for (int c = 0; c < nch; c++) {
        if (c + 1 < nch) loadc(c + 1);      // global prefetch overlaps MMA

#pragma unroll
        for (int ks = 0; ks < 2; ks++) {
            uint32_t fah[2][4], fal[2][4];
#pragma unroll
            for (int mi = 0; mi < 2; mi++) {
                uint32_t ro = (wm * 32 + mi * 16) * SA + ks * 32 + loff;
                ldm4(fah[mi], sAh + ro);
                ldm4(fal[mi], sAl + ro);
            }
#pragma unroll
            for (int nj = 0; nj < 4; nj++) {
                uint32_t ro = (wn * 64 + nj * 16) * SA + ks * 32 + loff;
                uint32_t bh[4], bl[4];
                ldm4(bh, sWh + ro);
                ldm4(bl, sWl + ro);
#pragma unroll
                for (int mi = 0; mi < 2; mi++) {
                    mma16816(acc[mi][2 * nj],     fah[mi], bh[0], bh[2]);
                    mma16816(acc[mi][2 * nj],     fah[mi], bl[0], bl[2]);
                    mma16816(acc[mi][2 * nj],     fal[mi], bh[0], bh[2]);
                    mma16816(acc[mi][2 * nj + 1], fah[mi], bh[1], bh[3]);
                    mma16816(acc[mi][2 * nj + 1], fah[mi], bl[1], bl[3]);
                    mma16816(acc[mi][2 * nj + 1], fal[mi], bh[1], bh[3]);
                }
            }
        }
        if (c + 1 < nch) { __syncthreads(); storec(); __syncthreads(); }
    }

    // epilogue
    const int g8 = lane >> 2, t2 = (lane & 3) * 2;
#pragma unroll
    for (int mi = 0; mi < 2; mi++) {
        const int r0 = bm + wm * 32 + mi * 16 + g8;
#pragma unroll
        for (int j = 0; j < 8; j++) {
            const int cc = bn + wn * 64 + j * 8 + t2;
            float b0 = 0.0f, b1 = 0.0f;
            if (jb.bias) { b0 = jb.bias[cc]; b1 = jb.bias[cc + 1]; }
            float* p0 = jb.C + (size_t)r0 * jb.N + cc;
            float* p1 = p0 + (size_t)8 * jb.N;
            p0[0] = acc[mi][j][0] + b0; p0[1] = acc[mi][j][1] + b1;
            p1[0] = acc[mi][j][2] + b0; p1[1] = acc[mi][j][3] + b1;
        }
    }
}

// ---------------------------------------------------------------------------
// zgemm: 3 GEMMs (K=64) + fused epilogue pre = Z1*M1 + Z2*M2 + Z3 + bias
// block 128x64, 256 thr (8 warps 4m x 2n, warp tile 32x32 per gemm)
// ---------------------------------------------------------------------------
#define SZ 144                   // 64 bf16 + 8 pad
#define ZG_SMEM (2*128*SZ + 2*64*SZ)   // 55296

__global__ __launch_bounds__(256)
void zgemm_k(const float* __restrict__ wdzi, const float* __restrict__ wdzH,
             const float* __restrict__ wbz, const float* __restrict__ bias)
{
    const int bn = blockIdx.x * 64;
    const int bm = blockIdx.y * 128;
    char* Ah = dynsm;
    char* Al = dynsm + 128 * SZ;
    char* Wh = dynsm + 2 * 128 * SZ;
    char* Wl = dynsm + 2 * 128 * SZ + 64 * SZ;
    const uint32_t sAh = smem_u32(Ah), sAl = smem_u32(Al);
    const uint32_t sWh = smem_u32(Wh), sWl = smem_u32(Wl);

    const int tid = threadIdx.x;
    const int lane = tid & 31, wid = tid >> 5;
    const int wm = wid & 3, wn = wid >> 2;     // wn 0..1
    const uint32_t loff = ((lane & 7) + ((lane >> 3) & 1) * 8) * SZ + (lane >> 4) * 16;

    float acc[3][2][4][4];
#pragma unroll
    for (int g = 0; g < 3; g++)
#pragma unroll
        for (int i = 0; i < 2; i++)
#pragma unroll
            for (int j = 0; j < 4; j++)
#pragma unroll
                for (int k = 0; k < 4; k++) acc[g][i][j][k] = 0.0f;

    const float* Wsrc[3] = { wdzi, wdzH, wbz };

    for (int g = 0; g < 3; g++) {
        // A = g_z[:, g*64 : g*64+64], lda 192
#pragma unroll
        for (int i = 0; i < 8; i++) {
            int idx = tid + i * 256;
            int r = idx >> 4, f = idx & 15;
            float4 v = *reinterpret_cast<const float4*>(g_z + (size_t)(bm + r) * 192 + g * 64 + f * 4);
            uint2 h, l; cvt_hilo(v, h, l);
            uint32_t o = r * SZ + f * 8;
            *reinterpret_cast<uint2*>(Ah + o) = h;
            *reinterpret_cast<uint2*>(Al + o) = l;
        }
        // W: 64 rows x 64 cols
#pragma unroll
        for (int i = 0; i < 4; i++) {
            int idx = tid + i * 256;
            int r = idx >> 4, f = idx & 15;
            float4 v = *reinterpret_cast<const float4*>(Wsrc[g] + (size_t)(bn + r) * 64 + f * 4);
            uint2 h, l; cvt_hilo(v, h, l);
            uint32_t o = r * SZ + f * 8;
            *reinterpret_cast<uint2*>(Wh + o) = h;
            *reinterpret_cast<uint2*>(Wl + o) = l;
        }
        __syncthreads();

#pragma unroll
        for (int ks = 0; ks < 4; ks++) {
            uint32_t fah[2][4], fal[2][4];
#pragma unroll
            for (int mi = 0; mi < 2; mi++) {
                uint32_t ro = (wm * 32 + mi * 16) * SZ + ks * 32 + loff;
                ldm4(fah[mi], sAh + ro);
                ldm4(fal[mi], sAl + ro);
            }
#pragma unroll
            for (int nj = 0; nj < 2; nj++) {
                uint32_t ro = (wn * 32 + nj * 16) * SZ + ks * 32 + loff;
                uint32_t bh[4], bl[4];
                ldm4(bh, sWh + ro);
                ldm4(bl, sWl + ro);
#pragma unroll
                for (int mi = 0; mi < 2; mi++) {
                    mma16816(acc[g][mi][2 * nj],     fah[mi], bh[0], bh[2]);
                    mma16816(acc[g][mi][2 * nj],     fah[mi], bl[0], bl[2]);
                    mma16816(acc[g][mi][2 * nj],     fal[mi], bh[0], bh[2]);
                    mma16816(acc[g][mi][2 * nj + 1], fah[mi], bh[1], bh[3]);
                    mma16816(acc[g][mi][2 * nj + 1], fah[mi], bl[1], bl[3]);
                    mma16816(acc[g][mi][2 * nj + 1], fal[mi], bh[1], bh[3]);
                }
            }
        }
        __syncthreads();
    }

    // fused epilogue
    const int g8 = lane >> 2, t2 = (lane & 3) * 2;
#pragma unroll
    for (int mi = 0; mi < 2; mi++) {
        const int r0 = bm + wm * 32 + mi * 16 + g8;
#pragma unroll
        for (int j = 0; j < 4; j++) {
            const int cc = bn + wn * 32 + j * 8 + t2;
            const float b0 = bias[cc], b1 = bias[cc + 1];
#pragma unroll
            for (int hrow = 0; hrow < 2; hrow++) {
                const int r = r0 + hrow * 8;
                const size_t off = (size_t)r * 4096 + cc;
                float m1a = g_M1[off], m1b = g_M1[off + 1];
                float m2a = g_M2[off], m2b = g_M2[off + 1];
                g_pre[off]     = acc[0][mi][j][2 * hrow]     * m1a + acc[1][mi][j][2 * hrow]     * m2a + acc[2][mi][j][2 * hrow]     + b0;
                g_pre[off + 1] = acc[0][mi][j][2 * hrow + 1] * m1b + acc[1][mi][j][2 * hrow + 1] * m2b + acc[2][mi][j][2 * hrow + 1] + b1;
            }
        }
    }
}

// ---------------------------------------------------------------------------
// meta gates + z embeddings fused
// ---------------------------------------------------------------------------
__global__ __launch_bounds__(256) void metaz_k(
    const float* __restrict__ meta_c, float* __restrict__ out,
    const float* __restrict__ w_hzi, const float* __restrict__ w_hzH,
    const float* __restrict__ w_hzb,
    const float* __restrict__ bias_i, const float* __restrict__ bias_H)
{
    __shared__ float mh[8][256];
    const int b0 = blockIdx.x * 8;
    const int tid = threadIdx.x;
#pragma unroll
    for (int i = 0; i < 8; i++) {
        const int b = b0 + i;
        const float* row = g_metapre + (size_t)b * 1024;
        float mi = row[tid], mf = row[tid + 256], mg = row[tid + 512], mo = row[tid + 768];
        float c = sigm(mf) * meta_c[b * 256 + tid] + sigm(mi) * tanhf(mg);
        float h = sigm(mo) * tanhf(c);
        out[OFF_METAH + b * 256 + tid] = h;
        out[OFF_METAC + b * 256 + tid] = c;
        mh[i][tid] = h;
    }
    __syncthreads();
    if (tid < 192) {
        const float* wrow; float bv;
        if (tid < 64)       { wrow = w_hzi + (size_t)tid * 256;         bv = bias_i[tid]; }
        else if (tid < 128) { wrow = w_hzH + (size_t)(tid - 64) * 256;  bv = bias_H[tid - 64]; }
        else                { wrow = w_hzb + (size_t)(tid - 128) * 256; bv = 0.0f; }
        float acc[8];
#pragma unroll
        for (int r = 0; r < 8; r++) acc[r] = bv;
        for (int k4 = 0; k4 < 64; k4++) {
            float4 w = *reinterpret_cast<const float4*>(wrow + k4 * 4);
#pragma unroll
            for (int r = 0; r < 8; r++) {
                float4 h4 = *reinterpret_cast<const float4*>(&mh[r][k4 * 4]);
                acc[r] += w.x * h4.x + w.y * h4.y + w.z * h4.z + w.w * h4.w;
            }
        }
#pragma unroll
        for (int r = 0; r < 8; r++)
            g_z[(size_t)(b0 + r) * 192 + tid] = acc[r];
    }
}

// ---------------------------------------------------------------------------
// main gates
// ---------------------------------------------------------------------------
__global__ __launch_bounds__(256) void combine_k(const float* __restrict__ main_c,
                                                 float* __restrict__ out) {
    int idx = blockIdx.x * 256 + threadIdx.x;
    int b = idx >> 8, q = idx & 255;
    const float* pb = g_pre + (size_t)b * 4096 + q * 4;
    float4 gi = *reinterpret_cast<const float4*>(pb);
    float4 gf = *reinterpret_cast<const float4*>(pb + 1024);
    float4 gg = *reinterpret_cast<const float4*>(pb + 2048);
    float4 go = *reinterpret_cast<const float4*>(pb + 3072);
    float4 cc = *reinterpret_cast<const float4*>(main_c + (size_t)b * 1024 + q * 4);
    float4 c, h;
    c.x = sigm(gf.x) * cc.x + sigm(gi.x) * tanhf(gg.x); h.x = sigm(go.x) * tanhf(c.x);
    c.y = sigm(gf.y) * cc.y + sigm(gi.y) * tanhf(gg.y); h.y = sigm(go.y) * tanhf(c.y);
    c.z = sigm(gf.z) * cc.z + sigm(gi.z) * tanhf(gg.z); h.z = sigm(go.z) * tanhf(c.z);
    c.w = sigm(gf.w) * cc.w + sigm(gi.w) * tanhf(gg.w); h.w = sigm(go.w) * tanhf(c.w);
    *reinterpret_cast<float4*>(out + OFF_MAINC + (size_t)b * 1024 + q * 4) = c;
    *reinterpret_cast<float4*>(out + OFF_MAINH + (size_t)b * 1024 + q * 4) = h;
}

// ---------------------------------------------------------------------------
// launch
// ---------------------------------------------------------------------------
extern "C" void kernel_launch(void* const* d_in, const int* in_sizes, int n_in,
                              void* d_out, int out_size)
{
    const float* input      = (const float*)d_in[0];
    const float* main_h     = (const float*)d_in[1];
    const float* main_c     = (const float*)d_in[2];
    const float* meta_h     = (const float*)d_in[3];
    const float* meta_c     = (const float*)d_in[4];
    const int*   task       = (const int*)d_in[5];
    const float* w_iH       = (const float*)d_in[6];
    const float* w_HH       = (const float*)d_in[7];
    const float* w_ih       = (const float*)d_in[8];
    const float* w_hh       = (const float*)d_in[9];
    const float* w_hzi      = (const float*)d_in[10];
    const float* w_hzH      = (const float*)d_in[11];
    const float* w_hzb      = (const float*)d_in[12];
    const float* w_dziH     = (const float*)d_in[13];
    const float* w_dzHH     = (const float*)d_in[14];
    const float* w_bzH      = (const float*)d_in[15];
    const float* bias_i     = (const float*)d_in[16];
    const float* bias_H     = (const float*)d_in[17];
    const float* bias       = (const float*)d_in[18];
    const float* bias_hyper = (const float*)d_in[19];
    float* out = (float*)d_out;

    float *p_metapre, *p_M1, *p_M2;
    cudaGetSymbolAddress((void**)&p_metapre, g_metapre);
    cudaGetSymbolAddress((void**)&p_M1, g_M1);
    cudaGetSymbolAddress((void**)&p_M2, g_M2);

    cudaFuncSetAttribute(biggemm_k, cudaFuncAttributeMaxDynamicSharedMemorySize, BG_SMEM);
    cudaFuncSetAttribute(zgemm_k,   cudaFuncAttributeMaxDynamicSharedMemorySize, ZG_SMEM);

    Jobs3 J;
    // job0: metapre = [input|main_h|meta_h] @ [w_ih|w_hh]^T + bias_hyper
    J.j[0].a[0] = { input,  1024, 0 };
    J.j[0].a[1] = { main_h, 1024, 1024 };
    J.j[0].a[2] = { meta_h, 256,  2048 };
    J.j[0].na = 3;
    J.j[0].w[0] = { w_ih, 2048, 0 };
    J.j[0].w[1] = { w_hh, 256,  2048 };
    J.j[0].nw = 2;
    J.j[0].bias = bias_hyper; J.j[0].C = p_metapre;
    J.j[0].N = 1024; J.j[0].K = 2304;
    J.j[0].wTaskBase = nullptr; J.j[0].taskStride = 0;

    // job1: M1 = input @ W_iH[task]^T
    J.j[1].a[0] = { input, 1024, 0 }; J.j[1].na = 1;
    J.j[1].w[0] = { nullptr, 1024, 0 }; J.j[1].nw = 1;
    J.j[1].bias = nullptr; J.j[1].C = p_M1;
    J.j[1].N = 4096; J.j[1].K = 1024;
    J.j[1].wTaskBase = w_iH; J.j[1].taskStride = (long long)4096 * 1024;

    // job2: M2 = main_h @ W_HH[task]^T
    J.j[2].a[0] = { main_h, 1024, 0 }; J.j[2].na = 1;
    J.j[2].w[0] = { nullptr, 1024, 0 }; J.j[2].nw = 1;
    J.j[2].bias = nullptr; J.j[2].C = p_M2;
    J.j[2].N = 4096; J.j[2].K = 1024;
    J.j[2].wTaskBase = w_HH; J.j[2].taskStride = (long long)4096 * 1024;

    biggemm_k<<<dim3(32, 4, 3), 256, BG_SMEM>>>(J, task);
    metaz_k<<<64, 256>>>(meta_c, out, w_hzi, w_hzH, w_hzb, bias_i, bias_H);
    zgemm_k<<<dim3(64, 4), 256, ZG_SMEM>>>(w_dziH, w_dzHH, w_bzH, bias);
    combine_k<<<512, 256>>>(main_c, out);
}

// round 5
// speedup vs baseline: 3.6587x; 1.1444x over previous
#include <cuda_runtime.h>
#include <cuda_fp16.h>
#include <math.h>
#include <stdint.h>

// ---------------------------------------------------------------------------
// dims / output layout
// ---------------------------------------------------------------------------
#define OFF_MAINH 0
#define OFF_MAINC (512*1024)
#define OFF_METAH (2*512*1024)
#define OFF_METAC (2*512*1024 + 512*256)

__device__ float g_metapreA[512*1024];
__device__ float g_metapreB[512*1024];
__device__ float g_z[512*192];
__device__ float g_M1[512*4096];
__device__ float g_M2[512*4096];
__device__ float g_pre[512*4096];

__device__ __forceinline__ uint32_t smem_u32(const void* p) {
    uint32_t a;
    asm("{ .reg .u64 t; cvta.to.shared.u64 t, %1; cvt.u32.u64 %0, t; }"
        : "=r"(a) : "l"(p));
    return a;
}
__device__ __forceinline__ float sigm(float x) { return 1.0f / (1.0f + __expf(-x)); }

__device__ __forceinline__ void ldm4(uint32_t* q, uint32_t addr) {
    asm volatile("ldmatrix.sync.aligned.m8n8.x4.shared.b16 {%0,%1,%2,%3}, [%4];"
        : "=r"(q[0]), "=r"(q[1]), "=r"(q[2]), "=r"(q[3]) : "r"(addr));
}
// mma m16n8k16 fp16 -> f32
__device__ __forceinline__ void mma16816(float* d, const uint32_t* a, uint32_t b0, uint32_t b1) {
    asm volatile("mma.sync.aligned.m16n8k16.row.col.f32.f16.f16.f32 "
        "{%0,%1,%2,%3},{%4,%5,%6,%7},{%8,%9},{%0,%1,%2,%3};"
        : "+f"(d[0]), "+f"(d[1]), "+f"(d[2]), "+f"(d[3])
        : "r"(a[0]), "r"(a[1]), "r"(a[2]), "r"(a[3]), "r"(b0), "r"(b1));
}
__device__ __forceinline__ uint32_t pkh(__half a, __half b) {
    __half2 t(a, b);
    return *reinterpret_cast<uint32_t*>(&t);
}
// fp32x4 -> hi fp16x4 + lo fp16x4 (A operand: exact split)
__device__ __forceinline__ void cvt_hilo(float4 v, uint2& h, uint2& l) {
    __half hx = __float2half_rn(v.x);
    __half hy = __float2half_rn(v.y);
    __half hz = __float2half_rn(v.z);
    __half hw = __float2half_rn(v.w);
    __half lx = __float2half_rn(v.x - __half2float(hx));
    __half ly = __float2half_rn(v.y - __half2float(hy));
    __half lz = __float2half_rn(v.z - __half2float(hz));
    __half lw = __float2half_rn(v.w - __half2float(hw));
    h = make_uint2(pkh(hx, hy), pkh(hz, hw));
    l = make_uint2(pkh(lx, ly), pkh(lz, lw));
}
// fp32x4 -> fp16x4 (W operand: single rounding)
__device__ __forceinline__ uint2 cvt_h(float4 v) {
    return make_uint2(pkh(__float2half_rn(v.x), __float2half_rn(v.y)),
                      pkh(__float2half_rn(v.z), __float2half_rn(v.w)));
}

// ---------------------------------------------------------------------------
// biggemm: C[M,N] = A[M,K] @ W[N,K]^T (+bias), fp16 A-split 2-product
// block 128x128, BK=32, 256 thr (8 warps, warp tile 32x64), double-buffered
// ---------------------------------------------------------------------------
struct Seg { const float* p; int lda; int kstart; };
struct Job {
    Seg a[3]; int na;
    Seg w[2]; int nw;
    const float* bias;
    float* C;
    int N; int kbegin; int kend;
    const float* wTaskBase;
    long long taskStride;
};
struct Jobs4 { Job j[4]; };

#define SA 80                     // 32 fp16 = 64B + 16B pad
#define STG (3*128*SA)            // Ah, Al, Wh per stage = 30720
#define BG_SMEM (2*STG)           // 61440

extern __shared__ char dynsm[];

__global__ __launch_bounds__(256)
void biggemm_k(Jobs4 jobs, const int* __restrict__ taskp) {
    Job jb = jobs.j[blockIdx.z];
    const int bn = blockIdx.x * 128;
    if (bn >= jb.N) return;
    const int bm = blockIdx.y * 128;
    if (jb.wTaskBase)
        jb.w[0].p = jb.wTaskBase + (size_t)(*taskp) * jb.taskStride;

    const uint32_t sb = smem_u32(dynsm);
    const int tid = threadIdx.x;
    const int lane = tid & 31, wid = tid >> 5;
    const int wm = wid & 3, wn = wid >> 2;
    const uint32_t loff = ((lane & 7) + ((lane >> 3) & 1) * 8) * SA + (lane >> 4) * 16;

    float acc[2][8][4];
#pragma unroll
    for (int i = 0; i < 2; i++)
#pragma unroll
        for (int j = 0; j < 8; j++)
#pragma unroll
            for (int k = 0; k < 4; k++) acc[i][j][k] = 0.0f;

    const int nch = (jb.kend - jb.kbegin) / 32;
    float4 ra[4], rw[4];

    auto loadc = [&](int c) {
        const int k0 = jb.kbegin + c * 32;
        Seg sa = jb.a[0];
        if (jb.na > 1 && k0 >= jb.a[1].kstart) sa = jb.a[1];
        if (jb.na > 2 && k0 >= jb.a[2].kstart) sa = jb.a[2];
        Seg sw = jb.w[0];
        if (jb.nw > 1 && k0 >= jb.w[1].kstart) sw = jb.w[1];
        const int ka = k0 - sa.kstart, kw = k0 - sw.kstart;
#pragma unroll
        for (int i = 0; i < 4; i++) {
            int idx = tid + i * 256;
            int r = idx >> 3, f = idx & 7;
            ra[i] = *reinterpret_cast<const float4*>(sa.p + (size_t)(bm + r) * sa.lda + ka + f * 4);
            rw[i] = *reinterpret_cast<const float4*>(sw.p + (size_t)(bn + r) * sw.lda + kw + f * 4);
        }
    };
    auto storec = [&](int s) {
        char* Ah = dynsm + s * STG;
        char* Al = Ah + 128 * SA;
        char* Wh = Ah + 2 * 128 * SA;
#pragma unroll
        for (int i = 0; i < 4; i++) {
            int idx = tid + i * 256;
            int r = idx >> 3, f = idx & 7;
            uint32_t o = r * SA + f * 8;
            uint2 h, l;
            cvt_hilo(ra[i], h, l);
            *reinterpret_cast<uint2*>(Ah + o) = h;
            *reinterpret_cast<uint2*>(Al + o) = l;
            *reinterpret_cast<uint2*>(Wh + o) = cvt_h(rw[i]);
        }
    };

    loadc(0); storec(0); __syncthreads();

    for (int c = 0; c < nch; c++) {
        if (c + 1 < nch) loadc(c + 1);     // gmem prefetch overlaps MMA
        const uint32_t st = sb + (c & 1) * STG;
        const uint32_t sAh = st, sAl = st + 128 * SA, sWh = st + 2 * 128 * SA;

#pragma unroll
        for (int ks = 0; ks < 2; ks++) {
            uint32_t fah[2][4], fal[2][4];
#pragma unroll
            for (int mi = 0; mi < 2; mi++) {
                uint32_t ro = (wm * 32 + mi * 16) * SA + ks * 32 + loff;
                ldm4(fah[mi], sAh + ro);
                ldm4(fal[mi], sAl + ro);
            }
#pragma unroll
            for (int nj = 0; nj < 4; nj++) {
                uint32_t ro = (wn * 64 + nj * 16) * SA + ks * 32 + loff;
                uint32_t bh[4];
                ldm4(bh, sWh + ro);
#pragma unroll
                for (int mi = 0; mi < 2; mi++) {
                    mma16816(acc[mi][2 * nj],     fah[mi], bh[0], bh[2]);
                    mma16816(acc[mi][2 * nj],     fal[mi], bh[0], bh[2]);
                    mma16816(acc[mi][2 * nj + 1], fah[mi], bh[1], bh[3]);
                    mma16816(acc[mi][2 * nj + 1], fal[mi], bh[1], bh[3]);
                }
            }
        }
        if (c + 1 < nch) { storec((c + 1) & 1); __syncthreads(); }
    }

    // epilogue
    const int g8 = lane >> 2, t2 = (lane & 3) * 2;
#pragma unroll
    for (int mi = 0; mi < 2; mi++) {
        const int r0 = bm + wm * 32 + mi * 16 + g8;
#pragma unroll
        for (int j = 0; j < 8; j++) {
            const int cc = bn + wn * 64 + j * 8 + t2;
            float b0 = 0.0f, b1 = 0.0f;
            if (jb.bias) { b0 = jb.bias[cc]; b1 = jb.bias[cc + 1]; }
            float* p0 = jb.C + (size_t)r0 * jb.N + cc;
            float* p1 = p0 + (size_t)8 * jb.N;
            p0[0] = acc[mi][j][0] + b0; p0[1] = acc[mi][j][1] + b1;
            p1[0] = acc[mi][j][2] + b0; p1[1] = acc[mi][j][3] + b1;
        }
    }
}

// ---------------------------------------------------------------------------
// zgemm: 3 GEMMs (K=64, fp16 2-product) + fused epilogue
// pre = Z1*M1 + Z2*M2 + Z3 + bias.  block 128x64, 256 thr.
// ---------------------------------------------------------------------------
#define SZ 144                    // 64 fp16 = 128B + 16B pad
#define ZG_SMEM ((2*128 + 64)*SZ) // Ah, Al (128 rows) + Wh (64 rows) = 46080

__global__ __launch_bounds__(256)
void zgemm_k(const float* __restrict__ wdzi, const float* __restrict__ wdzH,
             const float* __restrict__ wbz, const float* __restrict__ bias)
{
    const int bn = blockIdx.x * 64;
    const int bm = blockIdx.y * 128;
    char* Ah = dynsm;
    char* Al = dynsm + 128 * SZ;
    char* Wh = dynsm + 2 * 128 * SZ;
    const uint32_t sAh = smem_u32(Ah), sAl = smem_u32(Al), sWh = smem_u32(Wh);

    const int tid = threadIdx.x;
    const int lane = tid & 31, wid = tid >> 5;
    const int wm = wid & 3, wn = wid >> 2;
    const uint32_t loff = ((lane & 7) + ((lane >> 3) & 1) * 8) * SZ + (lane >> 4) * 16;

    float acc[3][2][4][4];
#pragma unroll
    for (int g = 0; g < 3; g++)
#pragma unroll
        for (int i = 0; i < 2; i++)
#pragma unroll
            for (int j = 0; j < 4; j++)
#pragma unroll
                for (int k = 0; k < 4; k++) acc[g][i][j][k] = 0.0f;

    const float* Wsrc[3] = { wdzi, wdzH, wbz };

    for (int g = 0; g < 3; g++) {
#pragma unroll
        for (int i = 0; i < 8; i++) {
            int idx = tid + i * 256;
            int r = idx >> 4, f = idx & 15;
            float4 v = *reinterpret_cast<const float4*>(g_z + (size_t)(bm + r) * 192 + g * 64 + f * 4);
            uint2 h, l; cvt_hilo(v, h, l);
            uint32_t o = r * SZ + f * 8;
            *reinterpret_cast<uint2*>(Ah + o) = h;
            *reinterpret_cast<uint2*>(Al + o) = l;
        }
#pragma unroll
        for (int i = 0; i < 4; i++) {
            int idx = tid + i * 256;
            int r = idx >> 4, f = idx & 15;
            float4 v = *reinterpret_cast<const float4*>(Wsrc[g] + (size_t)(bn + r) * 64 + f * 4);
            *reinterpret_cast<uint2*>(Wh + r * SZ + f * 8) = cvt_h(v);
        }
        __syncthreads();

#pragma unroll
        for (int ks = 0; ks < 4; ks++) {
            uint32_t fah[2][4], fal[2][4];
#pragma unroll
            for (int mi = 0; mi < 2; mi++) {
                uint32_t ro = (wm * 32 + mi * 16) * SZ + ks * 32 + loff;
                ldm4(fah[mi], sAh + ro);
                ldm4(fal[mi], sAl + ro);
            }
#pragma unroll
            for (int nj = 0; nj < 2; nj++) {
                uint32_t ro = (wn * 32 + nj * 16) * SZ + ks * 32 + loff;
                uint32_t bh[4];
                ldm4(bh, sWh + ro);
#pragma unroll
                for (int mi = 0; mi < 2; mi++) {
                    mma16816(acc[g][mi][2 * nj],     fah[mi], bh[0], bh[2]);
                    mma16816(acc[g][mi][2 * nj],     fal[mi], bh[0], bh[2]);
                    mma16816(acc[g][mi][2 * nj + 1], fah[mi], bh[1], bh[3]);
                    mma16816(acc[g][mi][2 * nj + 1], fal[mi], bh[1], bh[3]);
                }
            }
        }
        __syncthreads();
    }

    // fused epilogue
    const int g8 = lane >> 2, t2 = (lane & 3) * 2;
#pragma unroll
    for (int mi = 0; mi < 2; mi++) {
        const int r0 = bm + wm * 32 + mi * 16 + g8;
#pragma unroll
        for (int j = 0; j < 4; j++) {
            const int cc = bn + wn * 32 + j * 8 + t2;
            const float b0 = bias[cc], b1 = bias[cc + 1];
#pragma unroll
            for (int hrow = 0; hrow < 2; hrow++) {
                const int r = r0 + hrow * 8;
                const size_t off = (size_t)r * 4096 + cc;
                float m1a = g_M1[off], m1b = g_M1[off + 1];
                float m2a = g_M2[off], m2b = g_M2[off + 1];
                g_pre[off]     = acc[0][mi][j][2 * hrow]     * m1a + acc[1][mi][j][2 * hrow]     * m2a + acc[2][mi][j][2 * hrow]     + b0;
                g_pre[off + 1] = acc[0][mi][j][2 * hrow + 1] * m1b + acc[1][mi][j][2 * hrow + 1] * m2b + acc[2][mi][j][2 * hrow + 1] + b1;
            }
        }
    }
}

// ---------------------------------------------------------------------------
// meta gates + z embeddings fused (sums the two split-K metapre buffers)
// ---------------------------------------------------------------------------
__global__ __launch_bounds__(256) void metaz_k(
    const float* __restrict__ meta_c, float* __restrict__ out,
    const float* __restrict__ w_hzi, const float* __restrict__ w_hzH,
    const float* __restrict__ w_hzb,
    const float* __restrict__ bias_i, const float* __restrict__ bias_H)
{
    __shared__ float mh[8][256];
    const int b0 = blockIdx.x * 8;
    const int tid = threadIdx.x;
#pragma unroll
    for (int i = 0; i < 8; i++) {
        const int b = b0 + i;
        const float* ra = g_metapreA + (size_t)b * 1024;
        const float* rb = g_metapreB + (size_t)b * 1024;
        float mi = ra[tid] + rb[tid];
        float mf = ra[tid + 256] + rb[tid + 256];
        float mg = ra[tid + 512] + rb[tid + 512];
        float mo = ra[tid + 768] + rb[tid + 768];
        float c = sigm(mf) * meta_c[b * 256 + tid] + sigm(mi) * tanhf(mg);
        float h = sigm(mo) * tanhf(c);
        out[OFF_METAH + b * 256 + tid] = h;
        out[OFF_METAC + b * 256 + tid] = c;
        mh[i][tid] = h;
    }
    __syncthreads();
    if (tid < 192) {
        const float* wrow; float bv;
        if (tid < 64)       { wrow = w_hzi + (size_t)tid * 256;         bv = bias_i[tid]; }
        else if (tid < 128) { wrow = w_hzH + (size_t)(tid - 64) * 256;  bv = bias_H[tid - 64]; }
        else                { wrow = w_hzb + (size_t)(tid - 128) * 256; bv = 0.0f; }
        float acc[8];
#pragma unroll
        for (int r = 0; r < 8; r++) acc[r] = bv;
        for (int k4 = 0; k4 < 64; k4++) {
            float4 w = *reinterpret_cast<const float4*>(wrow + k4 * 4);
#pragma unroll
            for (int r = 0; r < 8; r++) {
                float4 h4 = *reinterpret_cast<const float4*>(&mh[r][k4 * 4]);
                acc[r] += w.x * h4.x + w.y * h4.y + w.z * h4.z + w.w * h4.w;
            }
        }
#pragma unroll
        for (int r = 0; r < 8; r++)
            g_z[(size_t)(b0 + r) * 192 + tid] = acc[r];
    }
}

// ---------------------------------------------------------------------------
// main gates
// ---------------------------------------------------------------------------
__global__ __launch_bounds__(256) void combine_k(const float* __restrict__ main_c,
                                                 float* __restrict__ out) {
    int idx = blockIdx.x * 256 + threadIdx.x;
    int b = idx >> 8, q = idx & 255;
    const float* pb = g_pre + (size_t)b * 4096 + q * 4;
    float4 gi = *reinterpret_cast<const float4*>(pb);
    float4 gf = *reinterpret_cast<const float4*>(pb + 1024);
    float4 gg = *reinterpret_cast<const float4*>(pb + 2048);
    float4 go = *reinterpret_cast<const float4*>(pb + 3072);
    float4 cc = *reinterpret_cast<const float4*>(main_c + (size_t)b * 1024 + q * 4);
    float4 c, h;
    c.x = sigm(gf.x) * cc.x + sigm(gi.x) * tanhf(gg.x); h.x = sigm(go.x) * tanhf(c.x);
    c.y = sigm(gf.y) * cc.y + sigm(gi.y) * tanhf(gg.y); h.y = sigm(go.y) * tanhf(c.y);
    c.z = sigm(gf.z) * cc.z + sigm(gi.z) * tanhf(gg.z); h.z = sigm(go.z) * tanhf(c.z);
    c.w = sigm(gf.w) * cc.w + sigm(gi.w) * tanhf(gg.w); h.w = sigm(go.w) * tanhf(c.w);
    *reinterpret_cast<float4*>(out + OFF_MAINC + (size_t)b * 1024 + q * 4) = c;
    *reinterpret_cast<float4*>(out + OFF_MAINH + (size_t)b * 1024 + q * 4) = h;
}

// ---------------------------------------------------------------------------
// launch
// ---------------------------------------------------------------------------
extern "C" void kernel_launch(void* const* d_in, const int* in_sizes, int n_in,
                              void* d_out, int out_size)
{
    const float* input      = (const float*)d_in[0];
    const float* main_h     = (const float*)d_in[1];
    const float* main_c     = (const float*)d_in[2];
    const float* meta_h     = (const float*)d_in[3];
    const float* meta_c     = (const float*)d_in[4];
    const int*   task       = (const int*)d_in[5];
    const float* w_iH       = (const float*)d_in[6];
    const float* w_HH       = (const float*)d_in[7];
    const float* w_ih       = (const float*)d_in[8];
    const float* w_hh       = (const float*)d_in[9];
    const float* w_hzi      = (const float*)d_in[10];
    const float* w_hzH      = (const float*)d_in[11];
    const float* w_hzb      = (const float*)d_in[12];
    const float* w_dziH     = (const float*)d_in[13];
    const float* w_dzHH     = (const float*)d_in[14];
    const float* w_bzH      = (const float*)d_in[15];
    const float* bias_i     = (const float*)d_in[16];
    const float* bias_H     = (const float*)d_in[17];
    const float* bias       = (const float*)d_in[18];
    const float* bias_hyper = (const float*)d_in[19];
    float* out = (float*)d_out;

    float *p_metapreA, *p_metapreB, *p_M1, *p_M2;
    cudaGetSymbolAddress((void**)&p_metapreA, g_metapreA);
    cudaGetSymbolAddress((void**)&p_metapreB, g_metapreB);
    cudaGetSymbolAddress((void**)&p_M1, g_M1);
    cudaGetSymbolAddress((void**)&p_M2, g_M2);

    cudaFuncSetAttribute(biggemm_k, cudaFuncAttributeMaxDynamicSharedMemorySize, BG_SMEM);
    cudaFuncSetAttribute(zgemm_k,   cudaFuncAttributeMaxDynamicSharedMemorySize, ZG_SMEM);

    Jobs4 J;
    // job0a: metapre (K 0..1152) + bias_hyper -> g_metapreA
    J.j[0].a[0] = { input,  1024, 0 };
    J.j[0].a[1] = { main_h, 1024, 1024 };
    J.j[0].a[2] = { meta_h, 256,  2048 };
    J.j[0].na = 3;
    J.j[0].w[0] = { w_ih, 2048, 0 };
    J.j[0].w[1] = { w_hh, 256,  2048 };
    J.j[0].nw = 2;
    J.j[0].bias = bias_hyper; J.j[0].C = p_metapreA;
    J.j[0].N = 1024; J.j[0].kbegin = 0; J.j[0].kend = 1152;
    J.j[0].wTaskBase = nullptr; J.j[0].taskStride = 0;

    // job0b: metapre (K 1152..2304) -> g_metapreB
    J.j[1] = J.j[0];
    J.j[1].bias = nullptr; J.j[1].C = p_metapreB;
    J.j[1].kbegin = 1152; J.j[1].kend = 2304;

    // job1: M1 = input @ W_iH[task]^T
    J.j[2].a[0] = { input, 1024, 0 }; J.j[2].na = 1;
    J.j[2].w[0] = { nullptr, 1024, 0 }; J.j[2].nw = 1;
    J.j[2].bias = nullptr; J.j[2].C = p_M1;
    J.j[2].N = 4096; J.j[2].kbegin = 0; J.j[2].kend = 1024;
    J.j[2].wTaskBase = w_iH; J.j[2].taskStride = (long long)4096 * 1024;

    // job2: M2 = main_h @ W_HH[task]^T
    J.j[3].a[0] = { main_h, 1024, 0 }; J.j[3].na = 1;
    J.j[3].w[0] = { nullptr, 1024, 0 }; J.j[3].nw = 1;
    J.j[3].bias = nullptr; J.j[3].C = p_M2;
    J.j[3].N = 4096; J.j[3].kbegin = 0; J.j[3].kend = 1024;
    J.j[3].wTaskBase = w_HH; J.j[3].taskStride = (long long)4096 * 1024;

    biggemm_k<<<dim3(32, 4, 4), 256, BG_SMEM>>>(J, task);
    metaz_k<<<64, 256>>>(meta_c, out, w_hzi, w_hzH, w_hzb, bias_i, bias_H);
    zgemm_k<<<dim3(64, 4), 256, ZG_SMEM>>>(w_dziH, w_dzHH, w_bzH, bias);
    combine_k<<<512, 256>>>(main_c, out);
}

// round 6
// speedup vs baseline: 5.1780x; 1.4152x over previous
#include <cuda_runtime.h>
#include <cuda_fp16.h>
#include <math.h>
#include <stdint.h>

// ---------------------------------------------------------------------------
// dims / output layout
// ---------------------------------------------------------------------------
#define OFF_MAINH 0
#define OFF_MAINC (512*1024)
#define OFF_METAH (2*512*1024)
#define OFF_METAC (2*512*1024 + 512*256)

__device__ float g_metapreA[512*1024];
__device__ float g_metapreB[512*1024];
__device__ float g_z[512*192];
__device__ float g_M1[512*4096];
__device__ float g_M2[512*4096];
__device__ float g_pre[512*4096];

// fp16 staging (pre-converted once per launch)
__device__ __align__(16) __half g_xh16[512*2304];    // [input|main_h|meta_h]
__device__ __align__(16) __half g_Wm16[1024*2304];   // [w_ih|w_hh]
__device__ __align__(16) __half g_W116[4096*1024];   // w_iH[task]
__device__ __align__(16) __half g_W216[4096*1024];   // w_HH[task]

__device__ __forceinline__ uint32_t smem_u32(const void* p) {
    uint32_t a;
    asm("{ .reg .u64 t; cvta.to.shared.u64 t, %1; cvt.u32.u64 %0, t; }"
        : "=r"(a) : "l"(p));
    return a;
}
__device__ __forceinline__ float sigm(float x) { return 1.0f / (1.0f + __expf(-x)); }

__device__ __forceinline__ void ldm4(uint32_t* q, uint32_t addr) {
    asm volatile("ldmatrix.sync.aligned.m8n8.x4.shared.b16 {%0,%1,%2,%3}, [%4];"
        : "=r"(q[0]), "=r"(q[1]), "=r"(q[2]), "=r"(q[3]) : "r"(addr));
}
__device__ __forceinline__ void mma16816(float* d, const uint32_t* a, uint32_t b0, uint32_t b1) {
    asm volatile("mma.sync.aligned.m16n8k16.row.col.f32.f16.f16.f32 "
        "{%0,%1,%2,%3},{%4,%5,%6,%7},{%8,%9},{%0,%1,%2,%3};"
        : "+f"(d[0]), "+f"(d[1]), "+f"(d[2]), "+f"(d[3])
        : "r"(a[0]), "r"(a[1]), "r"(a[2]), "r"(a[3]), "r"(b0), "r"(b1));
}
__device__ __forceinline__ uint32_t pkh(__half a, __half b) {
    __half2 t(a, b);
    return *reinterpret_cast<uint32_t*>(&t);
}
__device__ __forceinline__ void cvt_hilo(float4 v, uint2& h, uint2& l) {
    __half hx = __float2half_rn(v.x), hy = __float2half_rn(v.y);
    __half hz = __float2half_rn(v.z), hw = __float2half_rn(v.w);
    __half lx = __float2half_rn(v.x - __half2float(hx));
    __half ly = __float2half_rn(v.y - __half2float(hy));
    __half lz = __float2half_rn(v.z - __half2float(hz));
    __half lw = __float2half_rn(v.w - __half2float(hw));
    h = make_uint2(pkh(hx, hy), pkh(hz, hw));
    l = make_uint2(pkh(lx, ly), pkh(lz, lw));
}
__device__ __forceinline__ uint2 cvt_h(float4 v) {
    return make_uint2(pkh(__float2half_rn(v.x), __float2half_rn(v.y)),
                      pkh(__float2half_rn(v.z), __float2half_rn(v.w)));
}
__device__ __forceinline__ uint4 cvt_h8(float4 a, float4 b) {
    uint2 x = cvt_h(a), y = cvt_h(b);
    return make_uint4(x.x, x.y, y.x, y.y);
}

// ---------------------------------------------------------------------------
// convert pass: fp32 inputs/weights -> fp16 staging buffers
// ---------------------------------------------------------------------------
#define NU_XH   (512*2304/8)       // 147456
#define NU_WM   (1024*2304/8)      // 294912
#define NU_W1   (4096*1024/8)      // 524288
#define NU_ALL  (NU_XH + NU_WM + 2*NU_W1)

__global__ __launch_bounds__(256) void conv_k(
    const float* __restrict__ input, const float* __restrict__ main_h,
    const float* __restrict__ meta_h,
    const float* __restrict__ w_ih, const float* __restrict__ w_hh,
    const float* __restrict__ w_iH, const float* __restrict__ w_HH,
    const int* __restrict__ taskp)
{
    const size_t tstride = (size_t)4096 * 1024;
    const float* w1 = w_iH + (size_t)(*taskp) * tstride;
    const float* w2 = w_HH + (size_t)(*taskp) * tstride;

    for (int u = blockIdx.x * 256 + threadIdx.x; u < NU_ALL; u += gridDim.x * 256) {
        const float* src;
        uint4* dst;
        if (u < NU_XH) {
            int b = u / 288, c = (u % 288) * 8;
            if (c < 1024)      src = input  + (size_t)b * 1024 + c;
            else if (c < 2048) src = main_h + (size_t)b * 1024 + (c - 1024);
            else               src = meta_h + (size_t)b * 256  + (c - 2048);
            dst = reinterpret_cast<uint4*>(g_xh16) + u;
        } else if (u < NU_XH + NU_WM) {
            int v = u - NU_XH;
            int n = v / 288, c = (v % 288) * 8;
            if (c < 2048) src = w_ih + (size_t)n * 2048 + c;
            else          src = w_hh + (size_t)n * 256 + (c - 2048);
            dst = reinterpret_cast<uint4*>(g_Wm16) + v;
        } else if (u < NU_XH + NU_WM + NU_W1) {
            int v = u - NU_XH - NU_WM;
            src = w1 + (size_t)v * 8;
            dst = reinterpret_cast<uint4*>(g_W116) + v;
        } else {
            int v = u - NU_XH - NU_WM - NU_W1;
            src = w2 + (size_t)v * 8;
            dst = reinterpret_cast<uint4*>(g_W216) + v;
        }
        float4 a = *reinterpret_cast<const float4*>(src);
        float4 b = *reinterpret_cast<const float4*>(src + 4);
        *dst = cvt_h8(a, b);
    }
}

// ---------------------------------------------------------------------------
// biggemm: C[M,N] = A[M,K] @ W[N,K]^T (+bias), pure fp16 mma.sync
// CTA 128x128, BK=32, 256 thr (8 warps, warp tile 32x64)
// cp.async 4-stage ring, one sync per chunk
// ---------------------------------------------------------------------------
struct Job16 {
    const __half* A; int lda; int aoff;
    const __half* W; int ldw; int woff;
    const float* bias;
    float* C;
    int N; int nch;
};
struct Jobs4 { Job16 j[4]; };

#define SA 80                       // 32 fp16 = 64B + 16B pad
#define STG (2*128*SA)              // A + W per stage = 20480
#define BG_SMEM (4*STG)             // 81920

extern __shared__ char dynsm[];

#define CP16(dst, src) \
    asm volatile("cp.async.ca.shared.global [%0], [%1], 16;" :: "r"(dst), "l"(src))
#define CP_COMMIT() asm volatile("cp.async.commit_group;" ::: "memory")
#define CP_WAIT2()  asm volatile("cp.async.wait_group 2;" ::: "memory")

__global__ __launch_bounds__(256)
void biggemm_k(Jobs4 jobs) {
    const Job16 jb = jobs.j[blockIdx.z];
    const int bn = blockIdx.x * 128;
    if (bn >= jb.N) return;
    const int bm = blockIdx.y * 128;

    const uint32_t sb = smem_u32(dynsm);
    const int tid = threadIdx.x;
    const int lane = tid & 31, wid = tid >> 5;
    const int wm = wid & 3, wn = wid >> 2;
    const uint32_t loff = ((lane & 7) + ((lane >> 3) & 1) * 8) * SA + (lane >> 4) * 16;

    // per-thread cp.async segments: A segs {tid, tid+256}, W segs {tid, tid+256}
    const int r0 = tid >> 2,  s0 = tid & 3;          // seg q = tid
    const int r1 = (tid + 256) >> 2, s1 = s0;        // seg q = tid+256
    const __half* agp0 = jb.A + (size_t)(bm + r0) * jb.lda + jb.aoff + s0 * 8;
    const __half* agp1 = jb.A + (size_t)(bm + r1) * jb.lda + jb.aoff + s1 * 8;
    const __half* wgp0 = jb.W + (size_t)(bn + r0) * jb.ldw + jb.woff + s0 * 8;
    const __half* wgp1 = jb.W + (size_t)(bn + r1) * jb.ldw + jb.woff + s1 * 8;
    const uint32_t ao0 = r0 * SA + s0 * 16, ao1 = r1 * SA + s1 * 16;

    auto issue = [&](int c) {
        const uint32_t st = sb + (c & 3) * STG;
        const int k = c * 32;
        CP16(st + ao0,               agp0 + k);
        CP16(st + ao1,               agp1 + k);
        CP16(st + 128 * SA + ao0,    wgp0 + k);
        CP16(st + 128 * SA + ao1,    wgp1 + k);
    };

    float acc[2][8][4];
#pragma unroll
    for (int i = 0; i < 2; i++)
#pragma unroll
        for (int j = 0; j < 8; j++)
#pragma unroll
            for (int k = 0; k < 4; k++) acc[i][j][k] = 0.0f;

    const int nch = jb.nch;
    issue(0); CP_COMMIT();
    issue(1); CP_COMMIT();
    issue(2); CP_COMMIT();

    for (int c = 0; c < nch; c++) {
        CP_WAIT2();              // stage c landed
        __syncthreads();         // all warps done with stage (c-1); safe to refill (c+3)&3
        if (c + 3 < nch) issue(c + 3);
        CP_COMMIT();             // empty commits at tail keep group numbering uniform

        const uint32_t sA = sb + (c & 3) * STG;
        const uint32_t sW = sA + 128 * SA;
#pragma unroll
        for (int ks = 0; ks < 2; ks++) {
            uint32_t fa[2][4];
#pragma unroll
            for (int mi = 0; mi < 2; mi++)
                ldm4(fa[mi], sA + (wm * 32 + mi * 16) * SA + ks * 32 + loff);
#pragma unroll
            for (int nj = 0; nj < 4; nj++) {
                uint32_t bh[4];
                ldm4(bh, sW + (wn * 64 + nj * 16) * SA + ks * 32 + loff);
#pragma unroll
                for (int mi = 0; mi < 2; mi++) {
                    mma16816(acc[mi][2 * nj],     fa[mi], bh[0], bh[2]);
                    mma16816(acc[mi][2 * nj + 1], fa[mi], bh[1], bh[3]);
                }
            }
        }
    }

    // epilogue
    const int g8 = lane >> 2, t2 = (lane & 3) * 2;
#pragma unroll
    for (int mi = 0; mi < 2; mi++) {
        const int rr = bm + wm * 32 + mi * 16 + g8;
#pragma unroll
        for (int j = 0; j < 8; j++) {
            const int cc = bn + wn * 64 + j * 8 + t2;
            float b0 = 0.0f, b1 = 0.0f;
            if (jb.bias) { b0 = jb.bias[cc]; b1 = jb.bias[cc + 1]; }
            float* p0 = jb.C + (size_t)rr * jb.N + cc;
            float* p1 = p0 + (size_t)8 * jb.N;
            p0[0] = acc[mi][j][0] + b0; p0[1] = acc[mi][j][1] + b1;
            p1[0] = acc[mi][j][2] + b0; p1[1] = acc[mi][j][3] + b1;
        }
    }
}

// ---------------------------------------------------------------------------
// zgemm: 3 GEMMs (K=64, fp16 A-split 2-product) + fused epilogue
// pre = Z1*M1 + Z2*M2 + Z3 + bias.  block 128x64, 256 thr.
// ---------------------------------------------------------------------------
#define SZ 144
#define ZG_SMEM ((2*128 + 64)*SZ)

__global__ __launch_bounds__(256)
void zgemm_k(const float* __restrict__ wdzi, const float* __restrict__ wdzH,
             const float* __restrict__ wbz, const float* __restrict__ bias)
{
    const int bn = blockIdx.x * 64;
    const int bm = blockIdx.y * 128;
    char* Ah = dynsm;
    char* Al = dynsm + 128 * SZ;
    char* Wh = dynsm + 2 * 128 * SZ;
    const uint32_t sAh = smem_u32(Ah), sAl = smem_u32(Al), sWh = smem_u32(Wh);

    const int tid = threadIdx.x;
    const int lane = tid & 31, wid = tid >> 5;
    const int wm = wid & 3, wn = wid >> 2;
    const uint32_t loff = ((lane & 7) + ((lane >> 3) & 1) * 8) * SZ + (lane >> 4) * 16;

    float acc[3][2][4][4];
#pragma unroll
    for (int g = 0; g < 3; g++)
#pragma unroll
        for (int i = 0; i < 2; i++)
#pragma unroll
            for (int j = 0; j < 4; j++)
#pragma unroll
                for (int k = 0; k < 4; k++) acc[g][i][j][k] = 0.0f;

    const float* Wsrc[3] = { wdzi, wdzH, wbz };

    for (int g = 0; g < 3; g++) {
#pragma unroll
        for (int i = 0; i < 8; i++) {
            int idx = tid + i * 256;
            int r = idx >> 4, f = idx & 15;
            float4 v = *reinterpret_cast<const float4*>(g_z + (size_t)(bm + r) * 192 + g * 64 + f * 4);
            uint2 h, l; cvt_hilo(v, h, l);
            uint32_t o = r * SZ + f * 8;
            *reinterpret_cast<uint2*>(Ah + o) = h;
            *reinterpret_cast<uint2*>(Al + o) = l;
        }
#pragma unroll
        for (int i = 0; i < 4; i++) {
            int idx = tid + i * 256;
            int r = idx >> 4, f = idx & 15;
            float4 v = *reinterpret_cast<const float4*>(Wsrc[g] + (size_t)(bn + r) * 64 + f * 4);
            *reinterpret_cast<uint2*>(Wh + r * SZ + f * 8) = cvt_h(v);
        }
        __syncthreads();

#pragma unroll
        for (int ks = 0; ks < 4; ks++) {
            uint32_t fah[2][4], fal[2][4];
#pragma unroll
            for (int mi = 0; mi < 2; mi++) {
                uint32_t ro = (wm * 32 + mi * 16) * SZ + ks * 32 + loff;
                ldm4(fah[mi], sAh + ro);
                ldm4(fal[mi], sAl + ro);
            }
#pragma unroll
            for (int nj = 0; nj < 2; nj++) {
                uint32_t ro = (wn * 32 + nj * 16) * SZ + ks * 32 + loff;
                uint32_t bh[4];
                ldm4(bh, sWh + ro);
#pragma unroll
                for (int mi = 0; mi < 2; mi++) {
                    mma16816(acc[g][mi][2 * nj],     fah[mi], bh[0], bh[2]);
                    mma16816(acc[g][mi][2 * nj],     fal[mi], bh[0], bh[2]);
                    mma16816(acc[g][mi][2 * nj + 1], fah[mi], bh[1], bh[3]);
                    mma16816(acc[g][mi][2 * nj + 1], fal[mi], bh[1], bh[3]);
                }
            }
        }
        __syncthreads();
    }

    const int g8 = lane >> 2, t2 = (lane & 3) * 2;
#pragma unroll
    for (int mi = 0; mi < 2; mi++) {
        const int r0 = bm + wm * 32 + mi * 16 + g8;
#pragma unroll
        for (int j = 0; j < 4; j++) {
            const int cc = bn + wn * 32 + j * 8 + t2;
            const float b0 = bias[cc], b1 = bias[cc + 1];
#pragma unroll
            for (int hrow = 0; hrow < 2; hrow++) {
                const int r = r0 + hrow * 8;
                const size_t off = (size_t)r * 4096 + cc;
                float m1a = g_M1[off], m1b = g_M1[off + 1];
                float m2a = g_M2[off], m2b = g_M2[off + 1];
                g_pre[off]     = acc[0][mi][j][2 * hrow]     * m1a + acc[1][mi][j][2 * hrow]     * m2a + acc[2][mi][j][2 * hrow]     + b0;
                g_pre[off + 1] = acc[0][mi][j][2 * hrow + 1] * m1b + acc[1][mi][j][2 * hrow + 1] * m2b + acc[2][mi][j][2 * hrow + 1] + b1;
            }
        }
    }
}

// ---------------------------------------------------------------------------
// meta gates + z embeddings fused (sums split-K metapre buffers)
// ---------------------------------------------------------------------------
__global__ __launch_bounds__(256) void metaz_k(
    const float* __restrict__ meta_c, float* __restrict__ out,
    const float* __restrict__ w_hzi, const float* __restrict__ w_hzH,
    const float* __restrict__ w_hzb,
    const float* __restrict__ bias_i, const float* __restrict__ bias_H)
{
    __shared__ float mh[8][256];
    const int b0 = blockIdx.x * 8;
    const int tid = threadIdx.x;
#pragma unroll
    for (int i = 0; i < 8; i++) {
        const int b = b0 + i;
        const float* ra = g_metapreA + (size_t)b * 1024;
        const float* rb = g_metapreB + (size_t)b * 1024;
        float mi = ra[tid] + rb[tid];
        float mf = ra[tid + 256] + rb[tid + 256];
        float mg = ra[tid + 512] + rb[tid + 512];
        float mo = ra[tid + 768] + rb[tid + 768];
        float c = sigm(mf) * meta_c[b * 256 + tid] + sigm(mi) * tanhf(mg);
        float h = sigm(mo) * tanhf(c);
        out[OFF_METAH + b * 256 + tid] = h;
        out[OFF_METAC + b * 256 + tid] = c;
        mh[i][tid] = h;
    }
    __syncthreads();
    if (tid < 192) {
        const float* wrow; float bv;
        if (tid < 64)       { wrow = w_hzi + (size_t)tid * 256;         bv = bias_i[tid]; }
        else if (tid < 128) { wrow = w_hzH + (size_t)(tid - 64) * 256;  bv = bias_H[tid - 64]; }
        else                { wrow = w_hzb + (size_t)(tid - 128) * 256; bv = 0.0f; }
        float acc[8];
#pragma unroll
        for (int r = 0; r < 8; r++) acc[r] = bv;
        for (int k4 = 0; k4 < 64; k4++) {
            float4 w = *reinterpret_cast<const float4*>(wrow + k4 * 4);
#pragma unroll
            for (int r = 0; r < 8; r++) {
                float4 h4 = *reinterpret_cast<const float4*>(&mh[r][k4 * 4]);
                acc[r] += w.x * h4.x + w.y * h4.y + w.z * h4.z + w.w * h4.w;
            }
        }
#pragma unroll
        for (int r = 0; r < 8; r++)
            g_z[(size_t)(b0 + r) * 192 + tid] = acc[r];
    }
}

// ---------------------------------------------------------------------------
// main gates
// ---------------------------------------------------------------------------
__global__ __launch_bounds__(256) void combine_k(const float* __restrict__ main_c,
                                                 float* __restrict__ out) {
    int idx = blockIdx.x * 256 + threadIdx.x;
    int b = idx >> 8, q = idx & 255;
    const float* pb = g_pre + (size_t)b * 4096 + q * 4;
    float4 gi = *reinterpret_cast<const float4*>(pb);
    float4 gf = *reinterpret_cast<const float4*>(pb + 1024);
    float4 gg = *reinterpret_cast<const float4*>(pb + 2048);
    float4 go = *reinterpret_cast<const float4*>(pb + 3072);
    float4 cc = *reinterpret_cast<const float4*>(main_c + (size_t)b * 1024 + q * 4);
    float4 c, h;
    c.x = sigm(gf.x) * cc.x + sigm(gi.x) * tanhf(gg.x); h.x = sigm(go.x) * tanhf(c.x);
    c.y = sigm(gf.y) * cc.y + sigm(gi.y) * tanhf(gg.y); h.y = sigm(go.y) * tanhf(c.y);
    c.z = sigm(gf.z) * cc.z + sigm(gi.z) * tanhf(gg.z); h.z = sigm(go.z) * tanhf(c.z);
    c.w = sigm(gf.w) * cc.w + sigm(gi.w) * tanhf(gg.w); h.w = sigm(go.w) * tanhf(c.w);
    *reinterpret_cast<float4*>(out + OFF_MAINC + (size_t)b * 1024 + q * 4) = c;
    *reinterpret_cast<float4*>(out + OFF_MAINH + (size_t)b * 1024 + q * 4) = h;
}

// ---------------------------------------------------------------------------
// launch
// ---------------------------------------------------------------------------
extern "C" void kernel_launch(void* const* d_in, const int* in_sizes, int n_in,
                              void* d_out, int out_size)
{
    const float* input      = (const float*)d_in[0];
    const float* main_h     = (const float*)d_in[1];
    const float* main_c     = (const float*)d_in[2];
    const float* meta_h     = (const float*)d_in[3];
    const float* meta_c     = (const float*)d_in[4];
    const int*   task       = (const int*)d_in[5];
    const float* w_iH       = (const float*)d_in[6];
    const float* w_HH       = (const float*)d_in[7];
    const float* w_ih       = (const float*)d_in[8];
    const float* w_hh       = (const float*)d_in[9];
    const float* w_hzi      = (const float*)d_in[10];
    const float* w_hzH      = (const float*)d_in[11];
    const float* w_hzb      = (const float*)d_in[12];
    const float* w_dziH     = (const float*)d_in[13];
    const float* w_dzHH     = (const float*)d_in[14];
    const float* w_bzH      = (const float*)d_in[15];
    const float* bias_i     = (const float*)d_in[16];
    const float* bias_H     = (const float*)d_in[17];
    const float* bias       = (const float*)d_in[18];
    const float* bias_hyper = (const float*)d_in[19];
    float* out = (float*)d_out;

    float *p_metapreA, *p_metapreB, *p_M1, *p_M2;
    __half *p_xh16, *p_Wm16, *p_W116, *p_W216;
    cudaGetSymbolAddress((void**)&p_metapreA, g_metapreA);
    cudaGetSymbolAddress((void**)&p_metapreB, g_metapreB);
    cudaGetSymbolAddress((void**)&p_M1, g_M1);
    cudaGetSymbolAddress((void**)&p_M2, g_M2);
    cudaGetSymbolAddress((void**)&p_xh16, g_xh16);
    cudaGetSymbolAddress((void**)&p_Wm16, g_Wm16);
    cudaGetSymbolAddress((void**)&p_W116, g_W116);
    cudaGetSymbolAddress((void**)&p_W216, g_W216);

    cudaFuncSetAttribute(biggemm_k, cudaFuncAttributeMaxDynamicSharedMemorySize, BG_SMEM);
    cudaFuncSetAttribute(zgemm_k,   cudaFuncAttributeMaxDynamicSharedMemorySize, ZG_SMEM);

    conv_k<<<2912, 256>>>(input, main_h, meta_h, w_ih, w_hh, w_iH, w_HH, task);

    Jobs4 J;
    // j0a: metapre K[0,1152)  -> g_metapreA (+bias_hyper)
    J.j[0] = { p_xh16, 2304, 0,    p_Wm16, 2304, 0,    bias_hyper, p_metapreA, 1024, 36 };
    // j0b: metapre K[1152,2304) -> g_metapreB
    J.j[1] = { p_xh16, 2304, 1152, p_Wm16, 2304, 1152, nullptr,    p_metapreB, 1024, 36 };
    // j1: M1 = input @ W_iH[task]^T
    J.j[2] = { p_xh16, 2304, 0,    p_W116, 1024, 0,    nullptr,    p_M1,       4096, 32 };
    // j2: M2 = main_h @ W_HH[task]^T
    J.j[3] = { p_xh16, 2304, 1024, p_W216, 1024, 0,    nullptr,    p_M2,       4096, 32 };

    biggemm_k<<<dim3(32, 4, 4), 256, BG_SMEM>>>(J);
    metaz_k<<<64, 256>>>(meta_c, out, w_hzi, w_hzH, w_hzb, bias_i, bias_H);
    zgemm_k<<<dim3(64, 4), 256, ZG_SMEM>>>(w_dziH, w_dzHH, w_bzH, bias);
    combine_k<<<512, 256>>>(main_c, out);
}